// round 9
// baseline (speedup 1.0000x reference)
#include <cuda_runtime.h>
#include <cstdint>

// Problem constants
#define NS 131072
#define DD 16
#define RR 32
#define OO 10
#define EPSV 1e-8f

#define TPB 256
#define SPC 128            // samples per CTA (8 warps x 16)
#define GRID (NS / SPC)    // 1024

// ---- smem layout (floats) ----
#define SMF_X    0                        // 128 x 24  (x[16] | 1 | 0-pad)
#define SMF_CK   (SMF_X + 128 * 24)       // 32 x 32  (centers | -1/2s^2)
#define SMF_STR  (SMF_CK + 32 * 32)       // 128 x 33 strengths (pad 33)
#define SMF_B    (SMF_STR + 128 * 33)     // 40*3*32 float4: (bh0,bh1,bl0,bl1)
#define SMF_TOTAL (SMF_B + 40 * 3 * 32 * 4)
#define SMEM_BYTES (SMF_TOTAL * 4)        // 94720 B

// ---------------- helpers ----------------
__device__ __forceinline__ uint32_t tf32_hi(float v) {
    uint32_t r;
    asm("cvt.rna.tf32.f32 %0, %1;" : "=r"(r) : "f"(v));
    return r;
}
__device__ __forceinline__ long long pk2(float a, float b) {
    long long r;
    asm("mov.b64 %0, {%1, %2};" : "=l"(r) : "f"(a), "f"(b));
    return r;
}
__device__ __forceinline__ void unpk2(long long v, float& a, float& b) {
    asm("mov.b64 {%0, %1}, %2;" : "=f"(a), "=f"(b) : "l"(v));
}
__device__ __forceinline__ long long f2fma(long long a, long long b, long long c) {
    long long d;
    asm("fma.rn.f32x2 %0, %1, %2, %3;" : "=l"(d) : "l"(a), "l"(b), "l"(c));
    return d;
}
__device__ __forceinline__ long long f2sub(long long a, long long b) {
    long long d;
    asm("sub.rn.f32x2 %0, %1, %2;" : "=l"(d) : "l"(a), "l"(b));
    return d;
}
__device__ __forceinline__ long long f2mul(long long a, long long b) {
    long long d;
    asm("mul.rn.f32x2 %0, %1, %2;" : "=l"(d) : "l"(a), "l"(b));
    return d;
}
__device__ __forceinline__ long long f2add(long long a, long long b) {
    long long d;
    asm("add.rn.f32x2 %0, %1, %2;" : "=l"(d) : "l"(a), "l"(b));
    return d;
}

// m16n8k8 tf32 mma (sm_80 PTX -> legacy HMMA path, valid on plain sm_100)
__device__ __forceinline__ void mma_tf32(float c[4], const uint32_t a[4],
                                         uint32_t b0, uint32_t b1) {
    asm volatile(
        "mma.sync.aligned.m16n8k8.row.col.f32.tf32.tf32.f32 "
        "{%0,%1,%2,%3}, {%4,%5,%6,%7}, {%8,%9}, {%0,%1,%2,%3};"
        : "+f"(c[0]), "+f"(c[1]), "+f"(c[2]), "+f"(c[3])
        : "r"(a[0]), "r"(a[1]), "r"(a[2]), "r"(a[3]), "r"(b0), "r"(b1));
}

__device__ __forceinline__ void finish_sample(const float v_in[10], float ssum,
                                              float* __restrict__ outp) {
    float v[10];
    float inv = __fdividef(1.0f, ssum + EPSV);
    #pragma unroll
    for (int i = 0; i < 10; i++) v[i] = v_in[i] * inv;
    float m = v[0];
    #pragma unroll
    for (int i = 1; i < 10; i++) m = fmaxf(m, v[i]);
    float se = 0.0f;
    #pragma unroll
    for (int i = 0; i < 10; i++) { v[i] = __expf(v[i] - m); se += v[i]; }
    float is = __fdividef(1.0f, se);
    float2* o2 = (float2*)outp;  // row base 40B -> 8B aligned
    #pragma unroll
    for (int j = 0; j < 5; j++) {
        float2 w; w.x = v[2 * j] * is; w.y = v[2 * j + 1] * is;
        o2[j] = w;
    }
}

__global__ void __launch_bounds__(TPB, 2)
anfis_kernel(const float* __restrict__ X,
             const float* __restrict__ centers,
             const float* __restrict__ sigmas,
             const float* __restrict__ coeffs,
             float* __restrict__ out) {
    extern __shared__ float sm[];
    const int tid = threadIdx.x;
    const int lane = tid & 31;
    const int warp = tid >> 5;
    const int g = lane >> 2;   // group (row within tile)
    const int t = lane & 3;    // thread-in-group

    // ---- fill sX: 128 rows x (16 x | bias 1 | pad 0) ----
    {
        const float4* Xv = (const float4*)(X + (size_t)blockIdx.x * SPC * DD);
        for (int i = tid; i < SPC * 4; i += TPB) {
            int row = i >> 2, q = i & 3;
            *(float4*)(sm + SMF_X + row * 24 + q * 4) = Xv[i];
        }
        if (tid < SPC) {
            float* p = sm + SMF_X + tid * 24;
            p[16] = 1.0f;
            #pragma unroll
            for (int j = 17; j < 24; j++) p[j] = 0.0f;
        }
    }
    // ---- fill sCK ----
    for (int i = tid; i < RR * DD; i += TPB) {
        int r = i >> 4, d = i & 15;
        float sg = sigmas[i];
        sm[SMF_CK + r * 32 + d] = centers[i];
        sm[SMF_CK + r * 32 + 16 + d] = -0.5f / (sg * sg);
    }
    // ---- fill sB: fragment-ordered coeffs, tf32 hi/lo ----
    // n = o*32 + r (o-major). (nt,kt,lane): b0 at k=kt*8+t, b1 at k+4, col n=nt*8+g
    for (int i = tid; i < 40 * 3 * 32; i += TPB) {
        int l = i & 31, kt = (i >> 5) % 3, nt = i / 96;
        int tt = l & 3, gg = l >> 2;
        int n = nt * 8 + gg;
        int o = n >> 5, r = n & 31;
        int k0 = kt * 8 + tt, k1 = k0 + 4;
        float v0 = (k0 < 17) ? coeffs[(r * 17 + k0) * 10 + o] : 0.0f;
        float v1 = (k1 < 17) ? coeffs[(r * 17 + k1) * 10 + o] : 0.0f;
        uint32_t h0 = tf32_hi(v0), h1 = tf32_hi(v1);
        float l0 = v0 - __uint_as_float(h0);
        float l1 = v1 - __uint_as_float(h1);
        float4 w;
        w.x = __uint_as_float(h0);
        w.y = __uint_as_float(h1);
        w.z = __uint_as_float(tf32_hi(l0));
        w.w = __uint_as_float(tf32_hi(l1));
        *(float4*)(sm + SMF_B + (size_t)i * 4) = w;
    }
    __syncthreads();

    // ---- strengths: thread = (sample tid&127, rule-half tid>>7) ----
    {
        const int sample = tid & (SPC - 1);
        const int rb = (tid >> 7) << 4;
        const long long* xq = (const long long*)(sm + SMF_X + sample * 24);
        long long xp[8];
        #pragma unroll
        for (int j = 0; j < 8; j++) xp[j] = xq[j];
        #pragma unroll
        for (int ri = 0; ri < 16; ri++) {
            const int r = rb + ri;
            const longlong2* cp = (const longlong2*)(sm + SMF_CK + r * 32);
            const longlong2* kp = (const longlong2*)(sm + SMF_CK + r * 32 + 16);
            long long ea = 0LL, eb = 0LL;
            #pragma unroll
            for (int j = 0; j < 4; j++) {
                longlong2 cc = cp[j];
                longlong2 kk = kp[j];
                long long d0 = f2sub(xp[2 * j], cc.x);
                ea = f2fma(f2mul(d0, d0), kk.x, ea);
                long long d1 = f2sub(xp[2 * j + 1], cc.y);
                eb = f2fma(f2mul(d1, d1), kk.y, eb);
            }
            float e0, e1;
            unpk2(f2add(ea, eb), e0, e1);
            sm[SMF_STR + sample * 33 + r] = __expf(e0 + e1);
        }
    }
    __syncthreads();

    // ---- A fragments for this warp's 16 samples (rows ws+g, ws+g+8) ----
    const int ws = warp * 16;
    uint32_t ahi[3][4], alo[3][4];
    {
        const float* x0 = sm + SMF_X + (ws + g) * 24;
        const float* x1 = sm + SMF_X + (ws + g + 8) * 24;
        #pragma unroll
        for (int kt = 0; kt < 3; kt++) {
            int k0 = kt * 8 + t, k1 = k0 + 4;
            float v00 = x0[k0], v10 = x1[k0], v01 = x0[k1], v11 = x1[k1];
            ahi[kt][0] = tf32_hi(v00);
            ahi[kt][1] = tf32_hi(v10);
            ahi[kt][2] = tf32_hi(v01);
            ahi[kt][3] = tf32_hi(v11);
            alo[kt][0] = tf32_hi(v00 - __uint_as_float(ahi[kt][0]));
            alo[kt][1] = tf32_hi(v10 - __uint_as_float(ahi[kt][1]));
            alo[kt][2] = tf32_hi(v01 - __uint_as_float(ahi[kt][2]));
            alo[kt][3] = tf32_hi(v11 - __uint_as_float(ahi[kt][3]));
        }
    }

    // ---- strength cache: 8 r-values per row (r = rb8*8 + 2t + par) ----
    float s0[8], s1[8], ssum0 = 0.0f, ssum1 = 0.0f;
    {
        const float* st0 = sm + SMF_STR + (ws + g) * 33;
        const float* st1 = sm + SMF_STR + (ws + g + 8) * 33;
        #pragma unroll
        for (int j = 0; j < 8; j++) {
            int r = (j >> 1) * 8 + 2 * t + (j & 1);
            s0[j] = st0[r];
            s1[j] = st1[r];
            ssum0 += s0[j];
            ssum1 += s1[j];
        }
    }

    // ---- main GEMM + fused weighted-sum epilogue ----
    float out0[10], out1[10];
    #pragma unroll
    for (int i = 0; i < 10; i++) { out0[i] = 0.0f; out1[i] = 0.0f; }

    const float4* Bf = (const float4*)(sm + SMF_B);
    #pragma unroll 4
    for (int nt = 0; nt < 40; nt++) {
        float c[4] = {0.0f, 0.0f, 0.0f, 0.0f};
        #pragma unroll
        for (int kt = 0; kt < 3; kt++) {
            float4 bq = Bf[nt * 96 + kt * 32 + lane];
            uint32_t bh0 = __float_as_uint(bq.x), bh1 = __float_as_uint(bq.y);
            uint32_t bl0 = __float_as_uint(bq.z), bl1 = __float_as_uint(bq.w);
            mma_tf32(c, ahi[kt], bh0, bh1);
            mma_tf32(c, alo[kt], bh0, bh1);
            mma_tf32(c, ahi[kt], bl0, bl1);
        }
        const int o = nt >> 2;
        const int j2 = (nt & 3) * 2;
        out0[o] += s0[j2] * c[0] + s0[j2 + 1] * c[1];
        out1[o] += s1[j2] * c[2] + s1[j2 + 1] * c[3];
    }

    // ---- reduce across the 4 lanes of each group (t dimension) ----
    #pragma unroll
    for (int m = 1; m <= 2; m <<= 1) {
        #pragma unroll
        for (int i = 0; i < 10; i++) {
            out0[i] += __shfl_xor_sync(0xffffffffu, out0[i], m);
            out1[i] += __shfl_xor_sync(0xffffffffu, out1[i], m);
        }
        ssum0 += __shfl_xor_sync(0xffffffffu, ssum0, m);
        ssum1 += __shfl_xor_sync(0xffffffffu, ssum1, m);
    }

    // ---- finalize (t==0 lanes own rows ws+g and ws+g+8) ----
    if (t == 0) {
        const size_t base = (size_t)blockIdx.x * SPC;
        finish_sample(out0, ssum0, out + (base + ws + g) * OO);
        finish_sample(out1, ssum1, out + (base + ws + g + 8) * OO);
    }
}

extern "C" void kernel_launch(void* const* d_in, const int* in_sizes, int n_in,
                              void* d_out, int out_size) {
    const float* X = (const float*)d_in[0];
    const float* centers = (const float*)d_in[1];
    const float* sigmas = (const float*)d_in[2];
    const float* coeffs = (const float*)d_in[3];
    float* out = (float*)d_out;

    cudaFuncSetAttribute(anfis_kernel, cudaFuncAttributeMaxDynamicSharedMemorySize,
                         SMEM_BYTES);
    anfis_kernel<<<GRID, TPB, SMEM_BYTES>>>(X, centers, sigmas, coeffs, out);
}

// round 10
// speedup vs baseline: 1.0631x; 1.0631x over previous
#include <cuda_runtime.h>
#include <cstdint>

// Problem constants
#define NS 131072
#define DD 16
#define RR 32
#define OO 10
#define EPSV 1e-8f

#define TPB 256
#define SPC 128            // samples per CTA (8 warps x 16)
#define GRID (NS / SPC)    // 1024

// ---- smem layout (floats) ----
#define SMF_X    0                        // 128 x 24  (x[16] | 1 | 0-pad)
#define SMF_CK   (SMF_X + 128 * 24)       // 32 x 32  (centers | -1/2s^2)
#define SMF_STR  (SMF_CK + 32 * 32)       // 128 x 33 strengths (pad 33)
#define SMF_B    (SMF_STR + 128 * 33)     // 40*3*32 float2: (bh0,bh1)
#define SMF_TOTAL (SMF_B + 40 * 3 * 32 * 2)
#define SMEM_BYTES (SMF_TOTAL * 4)        // 64000 B -> 3 CTAs/SM

// ---------------- helpers ----------------
__device__ __forceinline__ uint32_t tf32_hi(float v) {
    uint32_t r;
    asm("cvt.rna.tf32.f32 %0, %1;" : "=r"(r) : "f"(v));
    return r;
}
__device__ __forceinline__ long long pk2(float a, float b) {
    long long r;
    asm("mov.b64 %0, {%1, %2};" : "=l"(r) : "f"(a), "f"(b));
    return r;
}
__device__ __forceinline__ void unpk2(long long v, float& a, float& b) {
    asm("mov.b64 {%0, %1}, %2;" : "=f"(a), "=f"(b) : "l"(v));
}
__device__ __forceinline__ long long f2fma(long long a, long long b, long long c) {
    long long d;
    asm("fma.rn.f32x2 %0, %1, %2, %3;" : "=l"(d) : "l"(a), "l"(b), "l"(c));
    return d;
}
__device__ __forceinline__ long long f2sub(long long a, long long b) {
    long long d;
    asm("sub.rn.f32x2 %0, %1, %2;" : "=l"(d) : "l"(a), "l"(b));
    return d;
}
__device__ __forceinline__ long long f2mul(long long a, long long b) {
    long long d;
    asm("mul.rn.f32x2 %0, %1, %2;" : "=l"(d) : "l"(a), "l"(b));
    return d;
}
__device__ __forceinline__ long long f2add(long long a, long long b) {
    long long d;
    asm("add.rn.f32x2 %0, %1, %2;" : "=l"(d) : "l"(a), "l"(b));
    return d;
}

// m16n8k8 tf32 mma (sm_80 PTX -> legacy HMMA path, valid on plain sm_100)
__device__ __forceinline__ void mma_tf32(float c[4], const uint32_t a[4],
                                         uint32_t b0, uint32_t b1) {
    asm volatile(
        "mma.sync.aligned.m16n8k8.row.col.f32.tf32.tf32.f32 "
        "{%0,%1,%2,%3}, {%4,%5,%6,%7}, {%8,%9}, {%0,%1,%2,%3};"
        : "+f"(c[0]), "+f"(c[1]), "+f"(c[2]), "+f"(c[3])
        : "r"(a[0]), "r"(a[1]), "r"(a[2]), "r"(a[3]), "r"(b0), "r"(b1));
}

__device__ __forceinline__ void finish_sample(const float v_in[10], float ssum,
                                              float* __restrict__ outp) {
    float v[10];
    float inv = __fdividef(1.0f, ssum + EPSV);
    #pragma unroll
    for (int i = 0; i < 10; i++) v[i] = v_in[i] * inv;
    float m = v[0];
    #pragma unroll
    for (int i = 1; i < 10; i++) m = fmaxf(m, v[i]);
    float se = 0.0f;
    #pragma unroll
    for (int i = 0; i < 10; i++) { v[i] = __expf(v[i] - m); se += v[i]; }
    float is = __fdividef(1.0f, se);
    float2* o2 = (float2*)outp;  // row base 40B -> 8B aligned
    #pragma unroll
    for (int j = 0; j < 5; j++) {
        float2 w; w.x = v[2 * j] * is; w.y = v[2 * j + 1] * is;
        o2[j] = w;
    }
}

__global__ void __launch_bounds__(TPB, 3)
anfis_kernel(const float* __restrict__ X,
             const float* __restrict__ centers,
             const float* __restrict__ sigmas,
             const float* __restrict__ coeffs,
             float* __restrict__ out) {
    extern __shared__ float sm[];
    const int tid = threadIdx.x;
    const int lane = tid & 31;
    const int warp = tid >> 5;
    const int g = lane >> 2;   // group (row within tile)
    const int t = lane & 3;    // thread-in-group

    // ---- fill sX: 128 rows x (16 x | bias 1 | pad 0) ----
    {
        const float4* Xv = (const float4*)(X + (size_t)blockIdx.x * SPC * DD);
        for (int i = tid; i < SPC * 4; i += TPB) {
            int row = i >> 2, q = i & 3;
            *(float4*)(sm + SMF_X + row * 24 + q * 4) = Xv[i];
        }
        if (tid < SPC) {
            float* p = sm + SMF_X + tid * 24;
            p[16] = 1.0f;
            #pragma unroll
            for (int j = 17; j < 24; j++) p[j] = 0.0f;
        }
    }
    // ---- fill sCK ----
    for (int i = tid; i < RR * DD; i += TPB) {
        int r = i >> 4, d = i & 15;
        float sg = sigmas[i];
        sm[SMF_CK + r * 32 + d] = centers[i];
        sm[SMF_CK + r * 32 + 16 + d] = -0.5f / (sg * sg);
    }
    // ---- fill sB: fragment-ordered coeff hi parts (tf32) ----
    // n = o*32 + r (o-major). (nt,kt,lane): b0 at k=kt*8+t, b1 at k+4, col n=nt*8+g
    for (int i = tid; i < 40 * 3 * 32; i += TPB) {
        int l = i & 31, kt = (i >> 5) % 3, nt = i / 96;
        int tt = l & 3, gg = l >> 2;
        int n = nt * 8 + gg;
        int o = n >> 5, r = n & 31;
        int k0 = kt * 8 + tt, k1 = k0 + 4;
        float v0 = (k0 < 17) ? coeffs[(r * 17 + k0) * 10 + o] : 0.0f;
        float v1 = (k1 < 17) ? coeffs[(r * 17 + k1) * 10 + o] : 0.0f;
        float2 w;
        w.x = __uint_as_float(tf32_hi(v0));
        w.y = __uint_as_float(tf32_hi(v1));
        *(float2*)(sm + SMF_B + (size_t)i * 2) = w;
    }
    __syncthreads();

    // ---- strengths: thread = (sample tid&127, rule-half tid>>7) ----
    {
        const int sample = tid & (SPC - 1);
        const int rb = (tid >> 7) << 4;
        const long long* xq = (const long long*)(sm + SMF_X + sample * 24);
        long long xp[8];
        #pragma unroll
        for (int j = 0; j < 8; j++) xp[j] = xq[j];
        #pragma unroll
        for (int ri = 0; ri < 16; ri++) {
            const int r = rb + ri;
            const longlong2* cp = (const longlong2*)(sm + SMF_CK + r * 32);
            const longlong2* kp = (const longlong2*)(sm + SMF_CK + r * 32 + 16);
            long long ea = 0LL, eb = 0LL;
            #pragma unroll
            for (int j = 0; j < 4; j++) {
                longlong2 cc = cp[j];
                longlong2 kk = kp[j];
                long long d0 = f2sub(xp[2 * j], cc.x);
                ea = f2fma(f2mul(d0, d0), kk.x, ea);
                long long d1 = f2sub(xp[2 * j + 1], cc.y);
                eb = f2fma(f2mul(d1, d1), kk.y, eb);
            }
            float e0, e1;
            unpk2(f2add(ea, eb), e0, e1);
            sm[SMF_STR + sample * 33 + r] = __expf(e0 + e1);
        }
    }
    __syncthreads();

    // ---- A fragments for this warp's 16 samples (rows ws+g, ws+g+8) ----
    const int ws = warp * 16;
    uint32_t ahi[3][4], alo[3][4];
    {
        const float* x0 = sm + SMF_X + (ws + g) * 24;
        const float* x1 = sm + SMF_X + (ws + g + 8) * 24;
        #pragma unroll
        for (int kt = 0; kt < 3; kt++) {
            int k0 = kt * 8 + t, k1 = k0 + 4;
            float v00 = x0[k0], v10 = x1[k0], v01 = x0[k1], v11 = x1[k1];
            ahi[kt][0] = tf32_hi(v00);
            ahi[kt][1] = tf32_hi(v10);
            ahi[kt][2] = tf32_hi(v01);
            ahi[kt][3] = tf32_hi(v11);
            alo[kt][0] = tf32_hi(v00 - __uint_as_float(ahi[kt][0]));
            alo[kt][1] = tf32_hi(v10 - __uint_as_float(ahi[kt][1]));
            alo[kt][2] = tf32_hi(v01 - __uint_as_float(ahi[kt][2]));
            alo[kt][3] = tf32_hi(v11 - __uint_as_float(ahi[kt][3]));
        }
    }

    // ---- strength cache: 8 r-values per row (r = rb8*8 + 2t + par) ----
    float s0[8], s1[8], ssum0 = 0.0f, ssum1 = 0.0f;
    {
        const float* st0 = sm + SMF_STR + (ws + g) * 33;
        const float* st1 = sm + SMF_STR + (ws + g + 8) * 33;
        #pragma unroll
        for (int j = 0; j < 8; j++) {
            int r = (j >> 1) * 8 + 2 * t + (j & 1);
            s0[j] = st0[r];
            s1[j] = st1[r];
            ssum0 += s0[j];
            ssum1 += s1[j];
        }
    }

    // ---- main GEMM + fused weighted-sum epilogue ----
    // 2-term tf32 compensation (hi*hi + lo*hi) in two INDEPENDENT accumulator
    // chains -> dependency depth 3 instead of 9 per tile.
    float out0[10], out1[10];
    #pragma unroll
    for (int i = 0; i < 10; i++) { out0[i] = 0.0f; out1[i] = 0.0f; }

    const float2* Bf = (const float2*)(sm + SMF_B);
    #pragma unroll 2
    for (int nt = 0; nt < 40; nt++) {
        float ch[4] = {0.0f, 0.0f, 0.0f, 0.0f};
        float cl[4] = {0.0f, 0.0f, 0.0f, 0.0f};
        #pragma unroll
        for (int kt = 0; kt < 3; kt++) {
            float2 bq = Bf[nt * 96 + kt * 32 + lane];
            uint32_t bh0 = __float_as_uint(bq.x), bh1 = __float_as_uint(bq.y);
            mma_tf32(ch, ahi[kt], bh0, bh1);
            mma_tf32(cl, alo[kt], bh0, bh1);
        }
        const int o = nt >> 2;
        const int j2 = (nt & 3) * 2;
        out0[o] += s0[j2] * (ch[0] + cl[0]) + s0[j2 + 1] * (ch[1] + cl[1]);
        out1[o] += s1[j2] * (ch[2] + cl[2]) + s1[j2 + 1] * (ch[3] + cl[3]);
    }

    // ---- reduce across the 4 lanes of each group (t dimension) ----
    #pragma unroll
    for (int m = 1; m <= 2; m <<= 1) {
        #pragma unroll
        for (int i = 0; i < 10; i++) {
            out0[i] += __shfl_xor_sync(0xffffffffu, out0[i], m);
            out1[i] += __shfl_xor_sync(0xffffffffu, out1[i], m);
        }
        ssum0 += __shfl_xor_sync(0xffffffffu, ssum0, m);
        ssum1 += __shfl_xor_sync(0xffffffffu, ssum1, m);
    }

    // ---- finalize (t==0 lanes own rows ws+g and ws+g+8) ----
    if (t == 0) {
        const size_t base = (size_t)blockIdx.x * SPC;
        finish_sample(out0, ssum0, out + (base + ws + g) * OO);
        finish_sample(out1, ssum1, out + (base + ws + g + 8) * OO);
    }
}

extern "C" void kernel_launch(void* const* d_in, const int* in_sizes, int n_in,
                              void* d_out, int out_size) {
    const float* X = (const float*)d_in[0];
    const float* centers = (const float*)d_in[1];
    const float* sigmas = (const float*)d_in[2];
    const float* coeffs = (const float*)d_in[3];
    float* out = (float*)d_out;

    cudaFuncSetAttribute(anfis_kernel, cudaFuncAttributeMaxDynamicSharedMemorySize,
                         SMEM_BYTES);
    anfis_kernel<<<GRID, TPB, SMEM_BYTES>>>(X, centers, sigmas, coeffs, out);
}

// round 11
// speedup vs baseline: 1.1838x; 1.1135x over previous
#include <cuda_runtime.h>
#include <cstdint>

// Problem constants
#define NS 131072
#define DD 16
#define RR 32
#define OO 10
#define EPSV 1e-8f

#define TPB 256
#define SPC 128            // samples per CTA (8 warps x 16)
#define GRID (NS / SPC)    // 1024

// ---- smem layout (floats) ----
#define SMF_X    0                         // 128 x 24  (x[16] | 0-pad)
#define SMF_CK   (SMF_X + 128 * 24)        // 32 x 32  (centers | -1/2s^2)
#define SMF_STR  (SMF_CK + 32 * 32)        // 128 x 33 strengths (pad 33)
#define SMF_B    (SMF_STR + 128 * 33)      // 40*2*32 float2 (bh0,bh1)
#define SMF_BIAS (SMF_B + 40 * 2 * 32 * 2) // 32 x 12 bias (o pad 10->12)
#define SMF_TOTAL (SMF_BIAS + 32 * 12)
#define SMEM_BYTES (SMF_TOTAL * 4)         // 55296 B -> 4 CTAs/SM

// ---------------- helpers ----------------
__device__ __forceinline__ uint32_t tf32_hi(float v) {
    uint32_t r;
    asm("cvt.rna.tf32.f32 %0, %1;" : "=r"(r) : "f"(v));
    return r;
}
__device__ __forceinline__ long long pk2(float a, float b) {
    long long r;
    asm("mov.b64 %0, {%1, %2};" : "=l"(r) : "f"(a), "f"(b));
    return r;
}
__device__ __forceinline__ void unpk2(long long v, float& a, float& b) {
    asm("mov.b64 {%0, %1}, %2;" : "=f"(a), "=f"(b) : "l"(v));
}
__device__ __forceinline__ long long f2fma(long long a, long long b, long long c) {
    long long d;
    asm("fma.rn.f32x2 %0, %1, %2, %3;" : "=l"(d) : "l"(a), "l"(b), "l"(c));
    return d;
}
__device__ __forceinline__ long long f2sub(long long a, long long b) {
    long long d;
    asm("sub.rn.f32x2 %0, %1, %2;" : "=l"(d) : "l"(a), "l"(b));
    return d;
}
__device__ __forceinline__ long long f2mul(long long a, long long b) {
    long long d;
    asm("mul.rn.f32x2 %0, %1, %2;" : "=l"(d) : "l"(a), "l"(b));
    return d;
}
__device__ __forceinline__ long long f2add(long long a, long long b) {
    long long d;
    asm("add.rn.f32x2 %0, %1, %2;" : "=l"(d) : "l"(a), "l"(b));
    return d;
}

// m16n8k8 tf32 mma (sm_80 PTX path, valid on plain sm_100)
__device__ __forceinline__ void mma_tf32(float c[4], const uint32_t a[4],
                                         uint32_t b0, uint32_t b1) {
    asm volatile(
        "mma.sync.aligned.m16n8k8.row.col.f32.tf32.tf32.f32 "
        "{%0,%1,%2,%3}, {%4,%5,%6,%7}, {%8,%9}, {%0,%1,%2,%3};"
        : "+f"(c[0]), "+f"(c[1]), "+f"(c[2]), "+f"(c[3])
        : "r"(a[0]), "r"(a[1]), "r"(a[2]), "r"(a[3]), "r"(b0), "r"(b1));
}

__device__ __forceinline__ void finish_sample(const float v_in[10], float ssum,
                                              float* __restrict__ outp) {
    float v[10];
    float inv = __fdividef(1.0f, ssum + EPSV);
    #pragma unroll
    for (int i = 0; i < 10; i++) v[i] = v_in[i] * inv;
    float m = v[0];
    #pragma unroll
    for (int i = 1; i < 10; i++) m = fmaxf(m, v[i]);
    float se = 0.0f;
    #pragma unroll
    for (int i = 0; i < 10; i++) { v[i] = __expf(v[i] - m); se += v[i]; }
    float is = __fdividef(1.0f, se);
    float2* o2 = (float2*)outp;  // row base 40B -> 8B aligned
    #pragma unroll
    for (int j = 0; j < 5; j++) {
        float2 w; w.x = v[2 * j] * is; w.y = v[2 * j + 1] * is;
        o2[j] = w;
    }
}

__global__ void __launch_bounds__(TPB, 4)
anfis_kernel(const float* __restrict__ X,
             const float* __restrict__ centers,
             const float* __restrict__ sigmas,
             const float* __restrict__ coeffs,
             float* __restrict__ out) {
    extern __shared__ float sm[];
    const int tid = threadIdx.x;
    const int lane = tid & 31;
    const int warp = tid >> 5;
    const int g = lane >> 2;   // group (row within tile)
    const int t = lane & 3;    // thread-in-group

    // ---- fill sX: 128 rows x (x[16] | 0-pad to 24) ----
    {
        const float4* Xv = (const float4*)(X + (size_t)blockIdx.x * SPC * DD);
        for (int i = tid; i < SPC * 4; i += TPB) {
            int row = i >> 2, q = i & 3;
            *(float4*)(sm + SMF_X + row * 24 + q * 4) = Xv[i];
        }
        if (tid < SPC) {
            float* p = sm + SMF_X + tid * 24;
            #pragma unroll
            for (int j = 16; j < 24; j++) p[j] = 0.0f;
        }
    }
    // ---- fill sCK ----
    for (int i = tid; i < RR * DD; i += TPB) {
        int r = i >> 4, d = i & 15;
        float sg = sigmas[i];
        sm[SMF_CK + r * 32 + d] = centers[i];
        sm[SMF_CK + r * 32 + 16 + d] = -0.5f / (sg * sg);
    }
    // ---- fill sB: fragment-ordered coeff hi parts (tf32), 2 k-tiles (k<16) ----
    // n = o*32 + r (o-major). (nt,kt,lane): b0 at k=kt*8+t, b1 at k+4, col n=nt*8+g
    for (int i = tid; i < 40 * 2 * 32; i += TPB) {
        int l = i & 31, kt = (i >> 5) & 1, nt = i >> 6;
        int tt = l & 3, gg = l >> 2;
        int n = nt * 8 + gg;
        int o = n >> 5, r = n & 31;
        int k0 = kt * 8 + tt, k1 = k0 + 4;
        float2 w;
        w.x = __uint_as_float(tf32_hi(coeffs[(r * 17 + k0) * 10 + o]));
        w.y = __uint_as_float(tf32_hi(coeffs[(r * 17 + k1) * 10 + o]));
        *(float2*)(sm + SMF_B + (size_t)i * 2) = w;
    }
    // ---- fill sBias: [r][o] o padded to 12, exact fp32 ----
    for (int i = tid; i < 32 * 12; i += TPB) {
        int r = i / 12, o = i - r * 12;
        sm[SMF_BIAS + i] = (o < 10) ? coeffs[(r * 17 + 16) * 10 + o] : 0.0f;
    }
    __syncthreads();

    // ---- strengths: thread = (sample tid&127, rule-half tid>>7) ----
    {
        const int sample = tid & (SPC - 1);
        const int rb = (tid >> 7) << 4;
        const long long* xq = (const long long*)(sm + SMF_X + sample * 24);
        long long xp[8];
        #pragma unroll
        for (int j = 0; j < 8; j++) xp[j] = xq[j];
        #pragma unroll
        for (int ri = 0; ri < 16; ri++) {
            const int r = rb + ri;
            const longlong2* cp = (const longlong2*)(sm + SMF_CK + r * 32);
            const longlong2* kp = (const longlong2*)(sm + SMF_CK + r * 32 + 16);
            long long ea = 0LL, eb = 0LL;
            #pragma unroll
            for (int j = 0; j < 4; j++) {
                longlong2 cc = cp[j];
                longlong2 kk = kp[j];
                long long d0 = f2sub(xp[2 * j], cc.x);
                ea = f2fma(f2mul(d0, d0), kk.x, ea);
                long long d1 = f2sub(xp[2 * j + 1], cc.y);
                eb = f2fma(f2mul(d1, d1), kk.y, eb);
            }
            float e0, e1;
            unpk2(f2add(ea, eb), e0, e1);
            sm[SMF_STR + sample * 33 + r] = __expf(e0 + e1);
        }
    }
    __syncthreads();

    // ---- A fragments (hi only) for rows ws+g, ws+g+8; 2 k-tiles, k<16 ----
    const int ws = warp * 16;
    uint32_t ahi[2][4];
    {
        const float* x0 = sm + SMF_X + (ws + g) * 24;
        const float* x1 = sm + SMF_X + (ws + g + 8) * 24;
        #pragma unroll
        for (int kt = 0; kt < 2; kt++) {
            int k0 = kt * 8 + t, k1 = k0 + 4;
            ahi[kt][0] = tf32_hi(x0[k0]);
            ahi[kt][1] = tf32_hi(x1[k0]);
            ahi[kt][2] = tf32_hi(x0[k1]);
            ahi[kt][3] = tf32_hi(x1[k1]);
        }
    }

    // ---- strength cache: 8 r-values per row (r = (j>>1)*8 + 2t + (j&1)) ----
    float s0[8], s1[8], ssum0 = 0.0f, ssum1 = 0.0f;
    {
        const float* st0 = sm + SMF_STR + (ws + g) * 33;
        const float* st1 = sm + SMF_STR + (ws + g + 8) * 33;
        #pragma unroll
        for (int j = 0; j < 8; j++) {
            int r = (j >> 1) * 8 + 2 * t + (j & 1);
            s0[j] = st0[r];
            s1[j] = st1[r];
            ssum0 += s0[j];
            ssum1 += s1[j];
        }
    }

    // ---- bias epilogue: out[o] = sum_j s[j] * b[r_j][o] (exact fp32) ----
    float out0[10], out1[10];
    #pragma unroll
    for (int i = 0; i < 10; i++) { out0[i] = 0.0f; out1[i] = 0.0f; }
    #pragma unroll
    for (int j = 0; j < 8; j++) {
        int r = (j >> 1) * 8 + 2 * t + (j & 1);
        const float* bp = sm + SMF_BIAS + r * 12;
        #pragma unroll
        for (int o = 0; o < 10; o++) {
            out0[o] += s0[j] * bp[o];
            out1[o] += s1[j] * bp[o];
        }
    }

    // ---- main GEMM (hi-only A and B; measured tf32 residual ~1e-4) ----
    const float2* Bf = (const float2*)(sm + SMF_B);
    #pragma unroll 2
    for (int nt = 0; nt < 40; nt++) {
        float c[4] = {0.0f, 0.0f, 0.0f, 0.0f};
        #pragma unroll
        for (int kt = 0; kt < 2; kt++) {
            float2 bq = Bf[nt * 64 + kt * 32 + lane];
            mma_tf32(c, ahi[kt], __float_as_uint(bq.x), __float_as_uint(bq.y));
        }
        const int o = nt >> 2;
        const int j2 = (nt & 3) * 2;
        out0[o] += s0[j2] * c[0] + s0[j2 + 1] * c[1];
        out1[o] += s1[j2] * c[2] + s1[j2 + 1] * c[3];
    }

    // ---- reduce across the 4 lanes of each group (t dimension) ----
    #pragma unroll
    for (int m = 1; m <= 2; m <<= 1) {
        #pragma unroll
        for (int i = 0; i < 10; i++) {
            out0[i] += __shfl_xor_sync(0xffffffffu, out0[i], m);
            out1[i] += __shfl_xor_sync(0xffffffffu, out1[i], m);
        }
        ssum0 += __shfl_xor_sync(0xffffffffu, ssum0, m);
        ssum1 += __shfl_xor_sync(0xffffffffu, ssum1, m);
    }

    // ---- finalize (t==0 lanes own rows ws+g and ws+g+8) ----
    if (t == 0) {
        const size_t base = (size_t)blockIdx.x * SPC;
        finish_sample(out0, ssum0, out + (base + ws + g) * OO);
        finish_sample(out1, ssum1, out + (base + ws + g + 8) * OO);
    }
}

extern "C" void kernel_launch(void* const* d_in, const int* in_sizes, int n_in,
                              void* d_out, int out_size) {
    const float* X = (const float*)d_in[0];
    const float* centers = (const float*)d_in[1];
    const float* sigmas = (const float*)d_in[2];
    const float* coeffs = (const float*)d_in[3];
    float* out = (float*)d_out;

    cudaFuncSetAttribute(anfis_kernel, cudaFuncAttributeMaxDynamicSharedMemorySize,
                         SMEM_BYTES);
    anfis_kernel<<<GRID, TPB, SMEM_BYTES>>>(X, centers, sigmas, coeffs, out);
}

// round 12
// speedup vs baseline: 1.6196x; 1.3681x over previous
#include <cuda_runtime.h>
#include <cstdint>

// Problem constants
#define NS 131072
#define DD 16
#define RR 32
#define OO 10
#define EPSV 1e-8f

#define TPB 256
#define SPC 128            // samples per CTA (8 warps x 16)
#define GRID (NS / SPC)    // 1024

// ---- smem layout (floats) ----
// A features (shared K=40 layout): k in [0,16): x_k^2 ; [16,32): x_{k-16} ;
//   k==32: 1 ; k in (32,40): 0
#define SMF_X    0                          // 128 x 24 raw x (pad 0)
#define SMF_GH   (SMF_X + 128 * 24)         // strength B hi: 4nt*5kt*32 float2
#define SMF_GL   (SMF_GH + 640 * 2)         // strength B lo
#define SMF_BA   (SMF_GL + 640 * 2)         // affine B hi: 40nt*3kt*32 float2
#define SMF_TOTAL (SMF_BA + 3840 * 2)
#define SMEM_BYTES (SMF_TOTAL * 4)          // 53376 B -> 3 CTAs/SM

// ---------------- helpers ----------------
__device__ __forceinline__ uint32_t tf32_hi(float v) {
    uint32_t r;
    asm("cvt.rna.tf32.f32 %0, %1;" : "=r"(r) : "f"(v));
    return r;
}

// m16n8k8 tf32 mma (sm_80 PTX path, valid on plain sm_100)
__device__ __forceinline__ void mma_tf32(float c[4], const uint32_t a[4],
                                         uint32_t b0, uint32_t b1) {
    asm volatile(
        "mma.sync.aligned.m16n8k8.row.col.f32.tf32.tf32.f32 "
        "{%0,%1,%2,%3}, {%4,%5,%6,%7}, {%8,%9}, {%0,%1,%2,%3};"
        : "+f"(c[0]), "+f"(c[1]), "+f"(c[2]), "+f"(c[3])
        : "r"(a[0]), "r"(a[1]), "r"(a[2]), "r"(a[3]), "r"(b0), "r"(b1));
}

// strength B element G[r][k]
__device__ __forceinline__ float gfeat(const float* __restrict__ centers,
                                       const float* __restrict__ sigmas,
                                       int r, int k) {
    if (k < 16) {
        float sg = sigmas[r * 16 + k];
        return -0.5f / (sg * sg);
    } else if (k < 32) {
        int d = k - 16;
        float sg = sigmas[r * 16 + d];
        float c = centers[r * 16 + d];
        return c / (sg * sg);
    } else if (k == 32) {
        float acc = 0.0f;
        #pragma unroll 4
        for (int d = 0; d < 16; d++) {
            float sg = sigmas[r * 16 + d];
            float c = centers[r * 16 + d];
            acc += -0.5f * c * c / (sg * sg);
        }
        return acc;
    }
    return 0.0f;
}

// affine B element: WI coeff for (rule r, out o, feature k)
__device__ __forceinline__ float afeat(const float* __restrict__ coeffs,
                                       int r, int o, int k) {
    if (k < 32) return coeffs[(r * 17 + (k - 16)) * 10 + o];  // k>=16 here
    if (k == 32) return coeffs[(r * 17 + 16) * 10 + o];       // bias
    return 0.0f;
}

__device__ __forceinline__ void finish_sample(const float v_in[10], float ssum,
                                              float* __restrict__ outp) {
    float v[10];
    float inv = __fdividef(1.0f, ssum + EPSV);
    #pragma unroll
    for (int i = 0; i < 10; i++) v[i] = v_in[i] * inv;
    float m = v[0];
    #pragma unroll
    for (int i = 1; i < 10; i++) m = fmaxf(m, v[i]);
    float se = 0.0f;
    #pragma unroll
    for (int i = 0; i < 10; i++) { v[i] = __expf(v[i] - m); se += v[i]; }
    float is = __fdividef(1.0f, se);
    float2* o2 = (float2*)outp;  // row base 40B -> 8B aligned
    #pragma unroll
    for (int j = 0; j < 5; j++) {
        float2 w; w.x = v[2 * j] * is; w.y = v[2 * j + 1] * is;
        o2[j] = w;
    }
}

__global__ void __launch_bounds__(TPB, 3)
anfis_kernel(const float* __restrict__ X,
             const float* __restrict__ centers,
             const float* __restrict__ sigmas,
             const float* __restrict__ coeffs,
             float* __restrict__ out) {
    extern __shared__ float sm[];
    const int tid = threadIdx.x;
    const int lane = tid & 31;
    const int warp = tid >> 5;
    const int g = lane >> 2;   // group (row within tile)
    const int t = lane & 3;    // thread-in-group

    // ---- fill sX ----
    {
        const float4* Xv = (const float4*)(X + (size_t)blockIdx.x * SPC * DD);
        for (int i = tid; i < SPC * 4; i += TPB) {
            int row = i >> 2, q = i & 3;
            *(float4*)(sm + SMF_X + row * 24 + q * 4) = Xv[i];
        }
        if (tid < SPC) {
            float* p = sm + SMF_X + tid * 24;
            #pragma unroll
            for (int j = 16; j < 24; j++) p[j] = 0.0f;
        }
    }
    // ---- fill strength B (G) hi/lo: (nt,kt,lane) b0 at k=kt*8+tt, b1 at k+4,
    //      col n = nt*8+gg = rule r ----
    for (int i = tid; i < 640; i += TPB) {
        int l = i & 31, kt = (i >> 5) % 5, nt = i / 160;
        int tt = l & 3, gg = l >> 2;
        int r = nt * 8 + gg;
        int k0 = kt * 8 + tt;
        float v0 = gfeat(centers, sigmas, r, k0);
        float v1 = gfeat(centers, sigmas, r, k0 + 4);
        uint32_t h0 = tf32_hi(v0), h1 = tf32_hi(v1);
        float2 wh, wl;
        wh.x = __uint_as_float(h0);
        wh.y = __uint_as_float(h1);
        wl.x = __uint_as_float(tf32_hi(v0 - __uint_as_float(h0)));
        wl.y = __uint_as_float(tf32_hi(v1 - __uint_as_float(h1)));
        *(float2*)(sm + SMF_GH + (size_t)i * 2) = wh;
        *(float2*)(sm + SMF_GL + (size_t)i * 2) = wl;
    }
    // ---- fill affine B hi: kt slots 0..2 = feature k-tiles 2..4;
    //      col n = nt*8+gg with n = o*32 + r ----
    for (int i = tid; i < 3840; i += TPB) {
        int l = i & 31, kt = (i >> 5) % 3, nt = i / 96;
        int tt = l & 3, gg = l >> 2;
        int n = nt * 8 + gg;
        int o = n >> 5, r = n & 31;
        int k0 = (kt + 2) * 8 + tt;
        float2 w;
        w.x = __uint_as_float(tf32_hi(afeat(coeffs, r, o, k0)));
        w.y = __uint_as_float(tf32_hi(afeat(coeffs, r, o, k0 + 4)));
        *(float2*)(sm + SMF_BA + (size_t)i * 2) = w;
    }
    __syncthreads();

    // ---- A fragments for rows ws+g, ws+g+8 over the K=40 feature layout ----
    const int ws = warp * 16;
    uint32_t sqh[2][4], sql[2][4], xh[2][4], xl[2][4], a4[4];
    {
        const float* x0 = sm + SMF_X + (ws + g) * 24;
        const float* x1 = sm + SMF_X + (ws + g + 8) * 24;
        #pragma unroll
        for (int kt = 0; kt < 2; kt++) {
            int k0 = kt * 8 + t, k1 = k0 + 4;
            float v00 = x0[k0], v10 = x1[k0], v01 = x0[k1], v11 = x1[k1];
            // x tiles (features 16..31)
            xh[kt][0] = tf32_hi(v00);
            xh[kt][1] = tf32_hi(v10);
            xh[kt][2] = tf32_hi(v01);
            xh[kt][3] = tf32_hi(v11);
            xl[kt][0] = tf32_hi(v00 - __uint_as_float(xh[kt][0]));
            xl[kt][1] = tf32_hi(v10 - __uint_as_float(xh[kt][1]));
            xl[kt][2] = tf32_hi(v01 - __uint_as_float(xh[kt][2]));
            xl[kt][3] = tf32_hi(v11 - __uint_as_float(xh[kt][3]));
            // x^2 tiles (features 0..15)
            float s00 = v00 * v00, s10 = v10 * v10, s01 = v01 * v01, s11 = v11 * v11;
            sqh[kt][0] = tf32_hi(s00);
            sqh[kt][1] = tf32_hi(s10);
            sqh[kt][2] = tf32_hi(s01);
            sqh[kt][3] = tf32_hi(s11);
            sql[kt][0] = tf32_hi(s00 - __uint_as_float(sqh[kt][0]));
            sql[kt][1] = tf32_hi(s10 - __uint_as_float(sqh[kt][1]));
            sql[kt][2] = tf32_hi(s01 - __uint_as_float(sqh[kt][2]));
            sql[kt][3] = tf32_hi(s11 - __uint_as_float(sqh[kt][3]));
        }
        uint32_t one = (t == 0) ? tf32_hi(1.0f) : 0u;
        a4[0] = one; a4[1] = one; a4[2] = 0u; a4[3] = 0u;
    }

    // ---- strength GEMM: e[row, r] = f(x) . G_r  (fully compensated) ----
    float s0[8], s1[8];
    float ssum0 = 0.0f, ssum1 = 0.0f;
    {
        const float2* Gh = (const float2*)(sm + SMF_GH);
        const float2* Gl = (const float2*)(sm + SMF_GL);
        #pragma unroll
        for (int nt = 0; nt < 4; nt++) {
            float ch[4] = {0.f, 0.f, 0.f, 0.f};
            float cl[4] = {0.f, 0.f, 0.f, 0.f};
            #pragma unroll
            for (int kt = 0; kt < 5; kt++) {
                float2 gh = Gh[(nt * 5 + kt) * 32 + lane];
                float2 gl = Gl[(nt * 5 + kt) * 32 + lane];
                uint32_t b0h = __float_as_uint(gh.x), b1h = __float_as_uint(gh.y);
                uint32_t b0l = __float_as_uint(gl.x), b1l = __float_as_uint(gl.y);
                const uint32_t* Ah = (kt < 2) ? sqh[kt] : (kt < 4) ? xh[kt - 2] : a4;
                mma_tf32(ch, Ah, b0h, b1h);
                mma_tf32(cl, Ah, b0l, b1l);
                if (kt < 4) {
                    const uint32_t* Al = (kt < 2) ? sql[kt] : xl[kt - 2];
                    mma_tf32(cl, Al, b0h, b1h);
                }
            }
            s0[nt * 2] = __expf(ch[0] + cl[0]);
            s0[nt * 2 + 1] = __expf(ch[1] + cl[1]);
            s1[nt * 2] = __expf(ch[2] + cl[2]);
            s1[nt * 2 + 1] = __expf(ch[3] + cl[3]);
            ssum0 += s0[nt * 2] + s0[nt * 2 + 1];
            ssum1 += s1[nt * 2] + s1[nt * 2 + 1];
        }
    }

    // ---- affine GEMM (hi-only, bias folded in at k=32) + fused epilogue ----
    float out0[10], out1[10];
    #pragma unroll
    for (int i = 0; i < 10; i++) { out0[i] = 0.0f; out1[i] = 0.0f; }
    {
        const float2* Bf = (const float2*)(sm + SMF_BA);
        #pragma unroll
        for (int nt = 0; nt < 40; nt++) {
            float c[4] = {0.f, 0.f, 0.f, 0.f};
            #pragma unroll
            for (int kt = 0; kt < 3; kt++) {
                float2 bq = Bf[(nt * 3 + kt) * 32 + lane];
                const uint32_t* Ah = (kt < 2) ? xh[kt] : a4;
                mma_tf32(c, Ah, __float_as_uint(bq.x), __float_as_uint(bq.y));
            }
            const int o = nt >> 2;          // compile-time under full unroll
            const int j2 = (nt & 3) * 2;
            out0[o] += s0[j2] * c[0] + s0[j2 + 1] * c[1];
            out1[o] += s1[j2] * c[2] + s1[j2 + 1] * c[3];
        }
    }

    // ---- reduce across the 4 lanes of each group (t dimension) ----
    #pragma unroll
    for (int m = 1; m <= 2; m <<= 1) {
        #pragma unroll
        for (int i = 0; i < 10; i++) {
            out0[i] += __shfl_xor_sync(0xffffffffu, out0[i], m);
            out1[i] += __shfl_xor_sync(0xffffffffu, out1[i], m);
        }
        ssum0 += __shfl_xor_sync(0xffffffffu, ssum0, m);
        ssum1 += __shfl_xor_sync(0xffffffffu, ssum1, m);
    }

    // ---- finalize (t==0 lanes own rows ws+g and ws+g+8) ----
    if (t == 0) {
        const size_t base = (size_t)blockIdx.x * SPC;
        finish_sample(out0, ssum0, out + (base + ws + g) * OO);
        finish_sample(out1, ssum1, out + (base + ws + g + 8) * OO);
    }
}

extern "C" void kernel_launch(void* const* d_in, const int* in_sizes, int n_in,
                              void* d_out, int out_size) {
    const float* X = (const float*)d_in[0];
    const float* centers = (const float*)d_in[1];
    const float* sigmas = (const float*)d_in[2];
    const float* coeffs = (const float*)d_in[3];
    float* out = (float*)d_out;

    cudaFuncSetAttribute(anfis_kernel, cudaFuncAttributeMaxDynamicSharedMemorySize,
                         SMEM_BYTES);
    anfis_kernel<<<GRID, TPB, SMEM_BYTES>>>(X, centers, sigmas, coeffs, out);
}

// round 13
// speedup vs baseline: 1.9117x; 1.1804x over previous
#include <cuda_runtime.h>
#include <cstdint>

// Problem constants
#define NS 131072
#define DD 16
#define RR 32
#define OO 10
#define EPSV 1e-8f

#define TPB 256
#define SPC 128            // samples per CTA (8 warps x 16)
#define GRID (NS / SPC)    // 1024

// Prebuilt B-fragment tables (written by prep_kernel, fragment-ordered)
__device__ __align__(16) float2 gGH[640];    // strength B hi  (4nt x 5kt x 32 lanes)
__device__ __align__(16) float2 gGL[640];    // strength B lo
__device__ __align__(16) float2 gBA[3840];   // affine  B hi  (40nt x 3kt x 32 lanes)

// ---------------- helpers ----------------
__device__ __forceinline__ uint32_t tf32_hi(float v) {
    uint32_t r;
    asm("cvt.rna.tf32.f32 %0, %1;" : "=r"(r) : "f"(v));
    return r;
}

// m16n8k8 tf32 mma (sm_80 PTX path, valid on plain sm_100)
__device__ __forceinline__ void mma_tf32(float c[4], const uint32_t a[4],
                                         uint32_t b0, uint32_t b1) {
    asm volatile(
        "mma.sync.aligned.m16n8k8.row.col.f32.tf32.tf32.f32 "
        "{%0,%1,%2,%3}, {%4,%5,%6,%7}, {%8,%9}, {%0,%1,%2,%3};"
        : "+f"(c[0]), "+f"(c[1]), "+f"(c[2]), "+f"(c[3])
        : "r"(a[0]), "r"(a[1]), "r"(a[2]), "r"(a[3]), "r"(b0), "r"(b1));
}

// strength B element G[r][k]  (features: [0,16)=x^2, [16,32)=x, 32=1)
__device__ float gfeat(const float* __restrict__ centers,
                       const float* __restrict__ sigmas, int r, int k) {
    if (k < 16) {
        float sg = sigmas[r * 16 + k];
        return -0.5f / (sg * sg);
    } else if (k < 32) {
        int d = k - 16;
        float sg = sigmas[r * 16 + d];
        return centers[r * 16 + d] / (sg * sg);
    } else if (k == 32) {
        float acc = 0.0f;
        for (int d = 0; d < 16; d++) {
            float sg = sigmas[r * 16 + d];
            float c = centers[r * 16 + d];
            acc += -0.5f * c * c / (sg * sg);
        }
        return acc;
    }
    return 0.0f;
}

// affine B element for (rule r, out o, feature k)
__device__ float afeat(const float* __restrict__ coeffs, int r, int o, int k) {
    if (k < 32) return coeffs[(r * 17 + (k - 16)) * 10 + o];  // k>=16 callers
    if (k == 32) return coeffs[(r * 17 + 16) * 10 + o];       // bias
    return 0.0f;
}

__global__ void prep_kernel(const float* __restrict__ centers,
                            const float* __restrict__ sigmas,
                            const float* __restrict__ coeffs) {
    int i = blockIdx.x * blockDim.x + threadIdx.x;
    if (i < 640) {
        int l = i & 31, kt = (i >> 5) % 5, nt = i / 160;
        int tt = l & 3, gg = l >> 2;
        int r = nt * 8 + gg;
        int k0 = kt * 8 + tt;
        float v0 = gfeat(centers, sigmas, r, k0);
        float v1 = gfeat(centers, sigmas, r, k0 + 4);
        uint32_t h0 = tf32_hi(v0), h1 = tf32_hi(v1);
        float2 wh, wl;
        wh.x = __uint_as_float(h0);
        wh.y = __uint_as_float(h1);
        wl.x = __uint_as_float(tf32_hi(v0 - __uint_as_float(h0)));
        wl.y = __uint_as_float(tf32_hi(v1 - __uint_as_float(h1)));
        gGH[i] = wh;
        gGL[i] = wl;
    }
    int j = i - 640;
    if (j >= 0 && j < 3840) {
        int l = j & 31, kt = (j >> 5) % 3, nt = j / 96;
        int tt = l & 3, gg = l >> 2;
        int n = nt * 8 + gg;
        int o = n >> 5, r = n & 31;
        int k0 = (kt + 2) * 8 + tt;
        float2 w;
        w.x = __uint_as_float(tf32_hi(afeat(coeffs, r, o, k0)));
        w.y = __uint_as_float(tf32_hi(afeat(coeffs, r, o, k0 + 4)));
        gBA[j] = w;
    }
}

__device__ __forceinline__ void finish_sample(const float v_in[10], float ssum,
                                              float* __restrict__ outp) {
    float v[10];
    float inv = __fdividef(1.0f, ssum + EPSV);
    #pragma unroll
    for (int i = 0; i < 10; i++) v[i] = v_in[i] * inv;
    float m = v[0];
    #pragma unroll
    for (int i = 1; i < 10; i++) m = fmaxf(m, v[i]);
    float se = 0.0f;
    #pragma unroll
    for (int i = 0; i < 10; i++) { v[i] = __expf(v[i] - m); se += v[i]; }
    float is = __fdividef(1.0f, se);
    float2* o2 = (float2*)outp;  // row base 40B -> 8B aligned
    #pragma unroll
    for (int j = 0; j < 5; j++) {
        float2 w; w.x = v[2 * j] * is; w.y = v[2 * j + 1] * is;
        o2[j] = w;
    }
}

__global__ void __launch_bounds__(TPB, 3)
anfis_kernel(const float* __restrict__ X, float* __restrict__ out) {
    __shared__ __align__(16) float smX[128 * 24];  // 12 KB, stride 24 floats
    const int tid = threadIdx.x;
    const int lane = tid & 31;
    const int warp = tid >> 5;
    const int g = lane >> 2;   // group (row within tile)
    const int t = lane & 3;    // thread-in-group

    // ---- stage X: 128 rows x 16 floats (stride 24) ----
    {
        const float4* Xv = (const float4*)(X + (size_t)blockIdx.x * SPC * DD);
        #pragma unroll
        for (int it = 0; it < 2; it++) {
            int i = tid + it * TPB;
            int row = i >> 2, q = i & 3;
            *(float4*)(smX + row * 24 + q * 4) = Xv[i];
        }
    }
    __syncthreads();

    // ---- A fragments for rows ws+g, ws+g+8 (features: x^2 | x | 1) ----
    const int ws = warp * 16;
    uint32_t sqh[2][4], sql[2][4], xh[2][4], xl[2][4], a4[4];
    {
        const float* x0 = smX + (ws + g) * 24;
        const float* x1 = smX + (ws + g + 8) * 24;
        #pragma unroll
        for (int kt = 0; kt < 2; kt++) {
            int k0 = kt * 8 + t, k1 = k0 + 4;
            float v00 = x0[k0], v10 = x1[k0], v01 = x0[k1], v11 = x1[k1];
            xh[kt][0] = tf32_hi(v00);
            xh[kt][1] = tf32_hi(v10);
            xh[kt][2] = tf32_hi(v01);
            xh[kt][3] = tf32_hi(v11);
            xl[kt][0] = tf32_hi(v00 - __uint_as_float(xh[kt][0]));
            xl[kt][1] = tf32_hi(v10 - __uint_as_float(xh[kt][1]));
            xl[kt][2] = tf32_hi(v01 - __uint_as_float(xh[kt][2]));
            xl[kt][3] = tf32_hi(v11 - __uint_as_float(xh[kt][3]));
            float s00 = v00 * v00, s10 = v10 * v10, s01 = v01 * v01, s11 = v11 * v11;
            sqh[kt][0] = tf32_hi(s00);
            sqh[kt][1] = tf32_hi(s10);
            sqh[kt][2] = tf32_hi(s01);
            sqh[kt][3] = tf32_hi(s11);
            sql[kt][0] = tf32_hi(s00 - __uint_as_float(sqh[kt][0]));
            sql[kt][1] = tf32_hi(s10 - __uint_as_float(sqh[kt][1]));
            sql[kt][2] = tf32_hi(s01 - __uint_as_float(sqh[kt][2]));
            sql[kt][3] = tf32_hi(s11 - __uint_as_float(sqh[kt][3]));
        }
        uint32_t one = (t == 0) ? tf32_hi(1.0f) : 0u;
        a4[0] = one; a4[1] = one; a4[2] = 0u; a4[3] = 0u;
    }

    // ---- strength GEMM: e[row, r] = f(x) . G_r  (fully compensated) ----
    float s0[8], s1[8];
    float ssum0 = 0.0f, ssum1 = 0.0f;
    #pragma unroll
    for (int nt = 0; nt < 4; nt++) {
        float ch[4] = {0.f, 0.f, 0.f, 0.f};
        float cl[4] = {0.f, 0.f, 0.f, 0.f};
        #pragma unroll
        for (int kt = 0; kt < 5; kt++) {
            float2 gh = __ldg(&gGH[(nt * 5 + kt) * 32 + lane]);
            float2 gl = __ldg(&gGL[(nt * 5 + kt) * 32 + lane]);
            uint32_t b0h = __float_as_uint(gh.x), b1h = __float_as_uint(gh.y);
            uint32_t b0l = __float_as_uint(gl.x), b1l = __float_as_uint(gl.y);
            const uint32_t* Ah = (kt < 2) ? sqh[kt] : (kt < 4) ? xh[kt - 2] : a4;
            mma_tf32(ch, Ah, b0h, b1h);
            mma_tf32(cl, Ah, b0l, b1l);
            if (kt < 4) {
                const uint32_t* Al = (kt < 2) ? sql[kt] : xl[kt - 2];
                mma_tf32(cl, Al, b0h, b1h);
            }
        }
        s0[nt * 2] = __expf(ch[0] + cl[0]);
        s0[nt * 2 + 1] = __expf(ch[1] + cl[1]);
        s1[nt * 2] = __expf(ch[2] + cl[2]);
        s1[nt * 2 + 1] = __expf(ch[3] + cl[3]);
        ssum0 += s0[nt * 2] + s0[nt * 2 + 1];
        ssum1 += s1[nt * 2] + s1[nt * 2 + 1];
    }

    // ---- affine GEMM (hi-only, bias folded at k=32) + fused epilogue ----
    float out0[10], out1[10];
    #pragma unroll
    for (int i = 0; i < 10; i++) { out0[i] = 0.0f; out1[i] = 0.0f; }
    #pragma unroll
    for (int nt = 0; nt < 40; nt++) {
        float c[4] = {0.f, 0.f, 0.f, 0.f};
        #pragma unroll
        for (int kt = 0; kt < 3; kt++) {
            float2 bq = __ldg(&gBA[(nt * 3 + kt) * 32 + lane]);
            const uint32_t* Ah = (kt < 2) ? xh[kt] : a4;
            mma_tf32(c, Ah, __float_as_uint(bq.x), __float_as_uint(bq.y));
        }
        const int o = nt >> 2;          // compile-time under full unroll
        const int j2 = (nt & 3) * 2;
        out0[o] += s0[j2] * c[0] + s0[j2 + 1] * c[1];
        out1[o] += s1[j2] * c[2] + s1[j2 + 1] * c[3];
    }

    // ---- reduce across the 4 lanes of each group (t dimension) ----
    #pragma unroll
    for (int m = 1; m <= 2; m <<= 1) {
        #pragma unroll
        for (int i = 0; i < 10; i++) {
            out0[i] += __shfl_xor_sync(0xffffffffu, out0[i], m);
            out1[i] += __shfl_xor_sync(0xffffffffu, out1[i], m);
        }
        ssum0 += __shfl_xor_sync(0xffffffffu, ssum0, m);
        ssum1 += __shfl_xor_sync(0xffffffffu, ssum1, m);
    }

    // ---- finalize (t==0 lanes own rows ws+g and ws+g+8) ----
    if (t == 0) {
        const size_t base = (size_t)blockIdx.x * SPC;
        finish_sample(out0, ssum0, out + (base + ws + g) * OO);
        finish_sample(out1, ssum1, out + (base + ws + g + 8) * OO);
    }
}

extern "C" void kernel_launch(void* const* d_in, const int* in_sizes, int n_in,
                              void* d_out, int out_size) {
    const float* X = (const float*)d_in[0];
    const float* centers = (const float*)d_in[1];
    const float* sigmas = (const float*)d_in[2];
    const float* coeffs = (const float*)d_in[3];
    float* out = (float*)d_out;

    prep_kernel<<<18, 256>>>(centers, sigmas, coeffs);
    anfis_kernel<<<GRID, TPB>>>(X, out);
}

// round 14
// speedup vs baseline: 2.1377x; 1.1182x over previous
#include <cuda_runtime.h>
#include <cstdint>

// Problem constants
#define NS 131072
#define DD 16
#define RR 32
#define OO 10
#define EPSV 1e-8f

#define TPB 256
#define SPC 128            // samples per CTA (8 warps x 16)
#define GRID (NS / SPC)    // 1024

// Prebuilt B-fragment tables (written by prep_kernel, fragment-ordered)
// gG4[i] = (hi.x, hi.y, lo.x, lo.y) for strength B  (4nt x 5kt x 32 lanes)
__device__ __align__(16) float4 gG4[640];
__device__ __align__(16) float2 gBA[3840];   // affine B hi (40nt x 3kt x 32 lanes)

// ---- smem layout (floats) ----
#define SMF_X   0                      // 128 x 24 raw x
#define SMF_G   (SMF_X + 128 * 24)     // 640 float4
#define SMF_BA  (SMF_G + 640 * 4)      // 3840 float2
#define SMF_TOTAL (SMF_BA + 3840 * 2)
#define SMEM_BYTES (SMF_TOTAL * 4)     // 53248 B -> 3 CTAs/SM

// ---------------- helpers ----------------
__device__ __forceinline__ uint32_t tf32_hi(float v) {
    uint32_t r;
    asm("cvt.rna.tf32.f32 %0, %1;" : "=r"(r) : "f"(v));
    return r;
}

// m16n8k8 tf32 mma (sm_80 PTX path, valid on plain sm_100)
__device__ __forceinline__ void mma_tf32(float c[4], const uint32_t a[4],
                                         uint32_t b0, uint32_t b1) {
    asm volatile(
        "mma.sync.aligned.m16n8k8.row.col.f32.tf32.tf32.f32 "
        "{%0,%1,%2,%3}, {%4,%5,%6,%7}, {%8,%9}, {%0,%1,%2,%3};"
        : "+f"(c[0]), "+f"(c[1]), "+f"(c[2]), "+f"(c[3])
        : "r"(a[0]), "r"(a[1]), "r"(a[2]), "r"(a[3]), "r"(b0), "r"(b1));
}

// strength B element G[r][k]  (features: [0,16)=x^2, [16,32)=x, 32=1)
__device__ float gfeat(const float* __restrict__ centers,
                       const float* __restrict__ sigmas, int r, int k) {
    if (k < 16) {
        float sg = sigmas[r * 16 + k];
        return -0.5f / (sg * sg);
    } else if (k < 32) {
        int d = k - 16;
        float sg = sigmas[r * 16 + d];
        return centers[r * 16 + d] / (sg * sg);
    } else if (k == 32) {
        float acc = 0.0f;
        for (int d = 0; d < 16; d++) {
            float sg = sigmas[r * 16 + d];
            float c = centers[r * 16 + d];
            acc += -0.5f * c * c / (sg * sg);
        }
        return acc;
    }
    return 0.0f;
}

// affine B element for (rule r, out o, feature k)
__device__ float afeat(const float* __restrict__ coeffs, int r, int o, int k) {
    if (k < 32) return coeffs[(r * 17 + (k - 16)) * 10 + o];
    if (k == 32) return coeffs[(r * 17 + 16) * 10 + o];       // bias
    return 0.0f;
}

__global__ void prep_kernel(const float* __restrict__ centers,
                            const float* __restrict__ sigmas,
                            const float* __restrict__ coeffs) {
    int i = blockIdx.x * blockDim.x + threadIdx.x;
    if (i < 640) {
        int l = i & 31, kt = (i >> 5) % 5, nt = i / 160;
        int tt = l & 3, gg = l >> 2;
        int r = nt * 8 + gg;
        int k0 = kt * 8 + tt;
        float v0 = gfeat(centers, sigmas, r, k0);
        float v1 = gfeat(centers, sigmas, r, k0 + 4);
        uint32_t h0 = tf32_hi(v0), h1 = tf32_hi(v1);
        float4 w;
        w.x = __uint_as_float(h0);
        w.y = __uint_as_float(h1);
        w.z = __uint_as_float(tf32_hi(v0 - __uint_as_float(h0)));
        w.w = __uint_as_float(tf32_hi(v1 - __uint_as_float(h1)));
        gG4[i] = w;
    }
    int j = i - 640;
    if (j >= 0 && j < 3840) {
        int l = j & 31, kt = (j >> 5) % 3, nt = j / 96;
        int tt = l & 3, gg = l >> 2;
        int n = nt * 8 + gg;
        int o = n >> 5, r = n & 31;
        int k0 = (kt + 2) * 8 + tt;
        float2 w;
        w.x = __uint_as_float(tf32_hi(afeat(coeffs, r, o, k0)));
        w.y = __uint_as_float(tf32_hi(afeat(coeffs, r, o, k0 + 4)));
        gBA[j] = w;
    }
}

__device__ __forceinline__ void finish_sample(const float v_in[10], float ssum,
                                              float* __restrict__ outp) {
    float v[10];
    float inv = __fdividef(1.0f, ssum + EPSV);
    #pragma unroll
    for (int i = 0; i < 10; i++) v[i] = v_in[i] * inv;
    float m = v[0];
    #pragma unroll
    for (int i = 1; i < 10; i++) m = fmaxf(m, v[i]);
    float se = 0.0f;
    #pragma unroll
    for (int i = 0; i < 10; i++) { v[i] = __expf(v[i] - m); se += v[i]; }
    float is = __fdividef(1.0f, se);
    float2* o2 = (float2*)outp;  // row base 40B -> 8B aligned
    #pragma unroll
    for (int j = 0; j < 5; j++) {
        float2 w; w.x = v[2 * j] * is; w.y = v[2 * j + 1] * is;
        o2[j] = w;
    }
}

__global__ void __launch_bounds__(TPB, 3)
anfis_kernel(const float* __restrict__ X, float* __restrict__ out) {
    extern __shared__ float sm[];
    const int tid = threadIdx.x;
    const int lane = tid & 31;
    const int warp = tid >> 5;
    const int g = lane >> 2;   // group (row within tile)
    const int t = lane & 3;    // thread-in-group

    // ---- stage X (128 rows x 16, stride 24) + copy B tables into smem ----
    {
        const float4* Xv = (const float4*)(X + (size_t)blockIdx.x * SPC * DD);
        #pragma unroll
        for (int it = 0; it < 2; it++) {
            int i = tid + it * TPB;
            int row = i >> 2, q = i & 3;
            *(float4*)(sm + SMF_X + row * 24 + q * 4) = Xv[i];
        }
        float4* dstG = (float4*)(sm + SMF_G);
        #pragma unroll
        for (int it = 0; it < 3; it++) {
            int i = tid + it * TPB;
            if (i < 640) dstG[i] = __ldg(&gG4[i]);
        }
        float4* dstB = (float4*)(sm + SMF_BA);
        const float4* srcB = (const float4*)gBA;
        #pragma unroll
        for (int it = 0; it < 8; it++) {
            int i = tid + it * TPB;
            if (i < 1920) dstB[i] = __ldg(&srcB[i]);
        }
    }
    __syncthreads();

    // ---- A fragments for rows ws+g, ws+g+8 (features: x^2 | x | 1) ----
    const int ws = warp * 16;
    uint32_t sqh[2][4], sql[2][4], xh[2][4], xl[2][4], a4[4];
    {
        const float* x0 = sm + SMF_X + (ws + g) * 24;
        const float* x1 = sm + SMF_X + (ws + g + 8) * 24;
        #pragma unroll
        for (int kt = 0; kt < 2; kt++) {
            int k0 = kt * 8 + t, k1 = k0 + 4;
            float v00 = x0[k0], v10 = x1[k0], v01 = x0[k1], v11 = x1[k1];
            xh[kt][0] = tf32_hi(v00);
            xh[kt][1] = tf32_hi(v10);
            xh[kt][2] = tf32_hi(v01);
            xh[kt][3] = tf32_hi(v11);
            xl[kt][0] = tf32_hi(v00 - __uint_as_float(xh[kt][0]));
            xl[kt][1] = tf32_hi(v10 - __uint_as_float(xh[kt][1]));
            xl[kt][2] = tf32_hi(v01 - __uint_as_float(xh[kt][2]));
            xl[kt][3] = tf32_hi(v11 - __uint_as_float(xh[kt][3]));
            float s00 = v00 * v00, s10 = v10 * v10, s01 = v01 * v01, s11 = v11 * v11;
            sqh[kt][0] = tf32_hi(s00);
            sqh[kt][1] = tf32_hi(s10);
            sqh[kt][2] = tf32_hi(s01);
            sqh[kt][3] = tf32_hi(s11);
            sql[kt][0] = tf32_hi(s00 - __uint_as_float(sqh[kt][0]));
            sql[kt][1] = tf32_hi(s10 - __uint_as_float(sqh[kt][1]));
            sql[kt][2] = tf32_hi(s01 - __uint_as_float(sqh[kt][2]));
            sql[kt][3] = tf32_hi(s11 - __uint_as_float(sqh[kt][3]));
        }
        uint32_t one = (t == 0) ? tf32_hi(1.0f) : 0u;
        a4[0] = one; a4[1] = one; a4[2] = 0u; a4[3] = 0u;
    }

    // ---- strength GEMM: e[row, r] = f(x) . G_r ----
    // 3 independent accumulator chains per nt: ch (Ah*Bh), cla (Ah*Bl), clb (Al*Bh)
    float s0[8], s1[8];
    float ssum0 = 0.0f, ssum1 = 0.0f;
    {
        const float4* Gf = (const float4*)(sm + SMF_G);
        #pragma unroll
        for (int nt = 0; nt < 4; nt++) {
            float ch[4] = {0.f, 0.f, 0.f, 0.f};
            float cla[4] = {0.f, 0.f, 0.f, 0.f};
            float clb[4] = {0.f, 0.f, 0.f, 0.f};
            #pragma unroll
            for (int kt = 0; kt < 5; kt++) {
                float4 gq = Gf[(nt * 5 + kt) * 32 + lane];
                uint32_t b0h = __float_as_uint(gq.x), b1h = __float_as_uint(gq.y);
                uint32_t b0l = __float_as_uint(gq.z), b1l = __float_as_uint(gq.w);
                const uint32_t* Ah = (kt < 2) ? sqh[kt] : (kt < 4) ? xh[kt - 2] : a4;
                mma_tf32(ch, Ah, b0h, b1h);
                mma_tf32(cla, Ah, b0l, b1l);
                if (kt < 4) {
                    const uint32_t* Al = (kt < 2) ? sql[kt] : xl[kt - 2];
                    mma_tf32(clb, Al, b0h, b1h);
                }
            }
            s0[nt * 2] = __expf(ch[0] + cla[0] + clb[0]);
            s0[nt * 2 + 1] = __expf(ch[1] + cla[1] + clb[1]);
            s1[nt * 2] = __expf(ch[2] + cla[2] + clb[2]);
            s1[nt * 2 + 1] = __expf(ch[3] + cla[3] + clb[3]);
            ssum0 += s0[nt * 2] + s0[nt * 2 + 1];
            ssum1 += s1[nt * 2] + s1[nt * 2 + 1];
        }
    }

    // ---- affine GEMM (hi-only, bias folded at k=32) + fused epilogue ----
    float out0[10], out1[10];
    #pragma unroll
    for (int i = 0; i < 10; i++) { out0[i] = 0.0f; out1[i] = 0.0f; }
    {
        const float2* Bf = (const float2*)(sm + SMF_BA);
        #pragma unroll
        for (int nt = 0; nt < 40; nt++) {
            float c[4] = {0.f, 0.f, 0.f, 0.f};
            #pragma unroll
            for (int kt = 0; kt < 3; kt++) {
                float2 bq = Bf[(nt * 3 + kt) * 32 + lane];
                const uint32_t* Ah = (kt < 2) ? xh[kt] : a4;
                mma_tf32(c, Ah, __float_as_uint(bq.x), __float_as_uint(bq.y));
            }
            const int o = nt >> 2;          // compile-time under full unroll
            const int j2 = (nt & 3) * 2;
            out0[o] += s0[j2] * c[0] + s0[j2 + 1] * c[1];
            out1[o] += s1[j2] * c[2] + s1[j2 + 1] * c[3];
        }
    }

    // ---- reduce across the 4 lanes of each group (t dimension) ----
    #pragma unroll
    for (int m = 1; m <= 2; m <<= 1) {
        #pragma unroll
        for (int i = 0; i < 10; i++) {
            out0[i] += __shfl_xor_sync(0xffffffffu, out0[i], m);
            out1[i] += __shfl_xor_sync(0xffffffffu, out1[i], m);
        }
        ssum0 += __shfl_xor_sync(0xffffffffu, ssum0, m);
        ssum1 += __shfl_xor_sync(0xffffffffu, ssum1, m);
    }

    // ---- finalize (t==0 lanes own rows ws+g and ws+g+8) ----
    if (t == 0) {
        const size_t base = (size_t)blockIdx.x * SPC;
        finish_sample(out0, ssum0, out + (base + ws + g) * OO);
        finish_sample(out1, ssum1, out + (base + ws + g + 8) * OO);
    }
}

extern "C" void kernel_launch(void* const* d_in, const int* in_sizes, int n_in,
                              void* d_out, int out_size) {
    const float* X = (const float*)d_in[0];
    const float* centers = (const float*)d_in[1];
    const float* sigmas = (const float*)d_in[2];
    const float* coeffs = (const float*)d_in[3];
    float* out = (float*)d_out;

    prep_kernel<<<18, 256>>>(centers, sigmas, coeffs);
    cudaFuncSetAttribute(anfis_kernel, cudaFuncAttributeMaxDynamicSharedMemorySize,
                         SMEM_BYTES);
    anfis_kernel<<<GRID, TPB, SMEM_BYTES>>>(X, out);
}

// round 15
// speedup vs baseline: 2.7957x; 1.3078x over previous
#include <cuda_runtime.h>
#include <cuda_fp16.h>
#include <cstdint>

// Problem constants
#define NS 131072
#define DD 16
#define RR 32
#define OO 10
#define EPSV 1e-8f

#define TPB 256
#define SPC 128            // samples per CTA (8 warps x 16)
#define GRID (NS / SPC)    // 1024

// ---- prebuilt fragment tables (prep_kernel output) ----
// Affine B (fp16 hi, K=16): [nt*32 + lane] -> (b0, b1)
__device__ __align__(16) uint2  gBF[1280];
// Affine bias (exact fp32): [nt*4 + t] -> (bias_n0, bias_n1), n0 = nt*8+2t
__device__ __align__(16) float2 gBias[160];
// Strength B (fp16 hi+lo): [(nt*2+kt)*32 + lane] -> (hi.b0, hi.b1, lo.b0, lo.b1)
__device__ __align__(16) uint4  gGF[256];
// Strength const (exact fp32): [nt*4 + t] -> (const_r0, const_r1), r0 = nt*8+2t
__device__ __align__(16) float2 gConst[16];

// ---------------- helpers ----------------
__device__ __forceinline__ uint32_t h2pk(float a, float b) {
    __half2 h = __floats2half2_rn(a, b);
    return *reinterpret_cast<uint32_t*>(&h);
}
__device__ __forceinline__ float hround(float v) {
    return __half2float(__float2half_rn(v));
}

// m16n8k16 fp16 mma, f32 accumulate (sm_80 PTX path, valid on plain sm_100)
__device__ __forceinline__ void mma_f16(float c[4], const uint32_t a[4],
                                        uint32_t b0, uint32_t b1) {
    asm volatile(
        "mma.sync.aligned.m16n8k16.row.col.f32.f16.f16.f32 "
        "{%0,%1,%2,%3}, {%4,%5,%6,%7}, {%8,%9}, {%0,%1,%2,%3};"
        : "+f"(c[0]), "+f"(c[1]), "+f"(c[2]), "+f"(c[3])
        : "r"(a[0]), "r"(a[1]), "r"(a[2]), "r"(a[3]), "r"(b0), "r"(b1));
}

// strength B element G[k][r]: k<16 -> x^2 coeff (-1/2s^2); k in [16,32) -> x coeff (c/s^2)
__device__ float gval(const float* __restrict__ centers,
                      const float* __restrict__ sigmas, int r, int k) {
    if (k < 16) {
        float sg = sigmas[r * 16 + k];
        return -0.5f / (sg * sg);
    }
    int d = k - 16;
    float sg = sigmas[r * 16 + d];
    return centers[r * 16 + d] / (sg * sg);
}

__global__ void prep_kernel(const float* __restrict__ centers,
                            const float* __restrict__ sigmas,
                            const float* __restrict__ coeffs) {
    int i = blockIdx.x * blockDim.x + threadIdx.x;

    // strength B fragments (fp16 hi+lo)
    if (i < 256) {
        int l = i & 31, kt = (i >> 5) & 1, nt = i >> 6;
        int t = l & 3, g = l >> 2;
        int r = nt * 8 + g;
        int kb = kt * 16;
        float v0 = gval(centers, sigmas, r, kb + 2 * t);
        float v1 = gval(centers, sigmas, r, kb + 2 * t + 1);
        float v8 = gval(centers, sigmas, r, kb + 2 * t + 8);
        float v9 = gval(centers, sigmas, r, kb + 2 * t + 9);
        uint4 w;
        w.x = h2pk(v0, v1);
        w.y = h2pk(v8, v9);
        w.z = h2pk(v0 - hround(v0), v1 - hround(v1));
        w.w = h2pk(v8 - hround(v8), v9 - hround(v9));
        gGF[i] = w;
    }
    // affine B fragments (fp16 hi, K=16)
    int j = i - 256;
    if (j >= 0 && j < 1280) {
        int l = j & 31, nt = j >> 5;
        int t = l & 3, g = l >> 2;
        int n = nt * 8 + g;
        int o = n >> 5, r = n & 31;
        int k = 2 * t;
        uint2 w;
        w.x = h2pk(coeffs[(r * 17 + k) * 10 + o], coeffs[(r * 17 + k + 1) * 10 + o]);
        w.y = h2pk(coeffs[(r * 17 + k + 8) * 10 + o], coeffs[(r * 17 + k + 9) * 10 + o]);
        gBF[j] = w;
    }
    // affine bias pairs (exact fp32)
    int b = i - (256 + 1280);
    if (b >= 0 && b < 160) {
        int nt = b >> 2, t = b & 3;
        int n0 = nt * 8 + 2 * t, n1 = n0 + 1;
        float2 w;
        w.x = coeffs[((n0 & 31) * 17 + 16) * 10 + (n0 >> 5)];
        w.y = coeffs[((n1 & 31) * 17 + 16) * 10 + (n1 >> 5)];
        gBias[b] = w;
    }
    // strength const pairs (exact fp32)
    int q = i - (256 + 1280 + 160);
    if (q >= 0 && q < 16) {
        int nt = q >> 2, t = q & 3;
        int r0 = nt * 8 + 2 * t;
        float2 w;
        float acc0 = 0.0f, acc1 = 0.0f;
        for (int d = 0; d < 16; d++) {
            float c0 = centers[r0 * 16 + d], s0 = sigmas[r0 * 16 + d];
            float c1 = centers[(r0 + 1) * 16 + d], s1 = sigmas[(r0 + 1) * 16 + d];
            acc0 += -0.5f * c0 * c0 / (s0 * s0);
            acc1 += -0.5f * c1 * c1 / (s1 * s1);
        }
        w.x = acc0; w.y = acc1;
        gConst[q] = w;
    }
}

__device__ __forceinline__ void finish_sample(const float v_in[10], float ssum,
                                              float* __restrict__ outp) {
    float v[10];
    float inv = __fdividef(1.0f, ssum + EPSV);
    #pragma unroll
    for (int i = 0; i < 10; i++) v[i] = v_in[i] * inv;
    float m = v[0];
    #pragma unroll
    for (int i = 1; i < 10; i++) m = fmaxf(m, v[i]);
    float se = 0.0f;
    #pragma unroll
    for (int i = 0; i < 10; i++) { v[i] = __expf(v[i] - m); se += v[i]; }
    float is = __fdividef(1.0f, se);
    float2* o2 = (float2*)outp;  // row base 40B -> 8B aligned
    #pragma unroll
    for (int j = 0; j < 5; j++) {
        float2 w; w.x = v[2 * j] * is; w.y = v[2 * j + 1] * is;
        o2[j] = w;
    }
}

__global__ void __launch_bounds__(TPB, 3)
anfis_kernel(const float* __restrict__ X, float* __restrict__ out) {
    __shared__ __align__(16) float  smX[128 * 24];   // 12 KB
    __shared__ __align__(16) uint2  sBF[1280];       // 10 KB
    __shared__ __align__(16) float2 sBias[160];      // 1.25 KB
    __shared__ __align__(16) uint4  sGF[256];        // 4 KB
    __shared__ __align__(16) float2 sConst[16];      // 128 B

    const int tid = threadIdx.x;
    const int lane = tid & 31;
    const int warp = tid >> 5;
    const int g = lane >> 2;   // group (row within tile)
    const int t = lane & 3;    // thread-in-group

    // ---- stage X + copy fragment tables to smem ----
    {
        const float4* Xv = (const float4*)(X + (size_t)blockIdx.x * SPC * DD);
        #pragma unroll
        for (int it = 0; it < 2; it++) {
            int i = tid + it * TPB;
            int row = i >> 2, q = i & 3;
            *(float4*)(smX + row * 24 + q * 4) = Xv[i];
        }
        uint4* dstBF = (uint4*)sBF;
        const uint4* srcBF = (const uint4*)gBF;
        #pragma unroll
        for (int it = 0; it < 3; it++) {
            int i = tid + it * TPB;
            if (i < 640) dstBF[i] = __ldg(&srcBF[i]);
        }
        if (tid < 256) sGF[tid] = __ldg(&gGF[tid]);
        if (tid < 80) ((float4*)sBias)[tid] = __ldg(&((const float4*)gBias)[tid]);
        if (tid < 8) ((float4*)sConst)[tid] = __ldg(&((const float4*)gConst)[tid]);
    }
    __syncthreads();

    // ---- A fragments for rows ws+g, ws+g+8 (fp16 hi/lo for x and x^2) ----
    const int ws = warp * 16;
    uint32_t xh[4], xl[4], sqh[4], sql[4];
    {
        const float* x0 = smX + (ws + g) * 24;
        const float* x1 = smX + (ws + g + 8) * 24;
        float2 p0 = *(const float2*)(x0 + 2 * t);
        float2 p0c = *(const float2*)(x0 + 2 * t + 8);
        float2 p1 = *(const float2*)(x1 + 2 * t);
        float2 p1c = *(const float2*)(x1 + 2 * t + 8);

        xh[0] = h2pk(p0.x, p0.y);
        xh[1] = h2pk(p1.x, p1.y);
        xh[2] = h2pk(p0c.x, p0c.y);
        xh[3] = h2pk(p1c.x, p1c.y);
        xl[0] = h2pk(p0.x - hround(p0.x), p0.y - hround(p0.y));
        xl[1] = h2pk(p1.x - hround(p1.x), p1.y - hround(p1.y));
        xl[2] = h2pk(p0c.x - hround(p0c.x), p0c.y - hround(p0c.y));
        xl[3] = h2pk(p1c.x - hround(p1c.x), p1c.y - hround(p1c.y));

        float q0x = p0.x * p0.x, q0y = p0.y * p0.y;
        float q1x = p1.x * p1.x, q1y = p1.y * p1.y;
        float q0cx = p0c.x * p0c.x, q0cy = p0c.y * p0c.y;
        float q1cx = p1c.x * p1c.x, q1cy = p1c.y * p1c.y;
        sqh[0] = h2pk(q0x, q0y);
        sqh[1] = h2pk(q1x, q1y);
        sqh[2] = h2pk(q0cx, q0cy);
        sqh[3] = h2pk(q1cx, q1cy);
        sql[0] = h2pk(q0x - hround(q0x), q0y - hround(q0y));
        sql[1] = h2pk(q1x - hround(q1x), q1y - hround(q1y));
        sql[2] = h2pk(q0cx - hround(q0cx), q0cy - hround(q0cy));
        sql[3] = h2pk(q1cx - hround(q1cx), q1cy - hround(q1cy));
    }

    // ---- strength GEMM: e = [x^2 | x] . G + const; 3 comp chains per nt ----
    float s0[8], s1[8];
    float ssum0 = 0.0f, ssum1 = 0.0f;
    #pragma unroll
    for (int nt = 0; nt < 4; nt++) {
        float2 cst = sConst[nt * 4 + t];
        float ch[4] = {cst.x, cst.y, cst.x, cst.y};
        float cla[4] = {0.f, 0.f, 0.f, 0.f};
        float clb[4] = {0.f, 0.f, 0.f, 0.f};
        #pragma unroll
        for (int kt = 0; kt < 2; kt++) {
            uint4 gq = sGF[(nt * 2 + kt) * 32 + lane];
            const uint32_t* Ah = (kt == 0) ? sqh : xh;
            const uint32_t* Al = (kt == 0) ? sql : xl;
            mma_f16(ch, Ah, gq.x, gq.y);
            mma_f16(cla, Ah, gq.z, gq.w);
            mma_f16(clb, Al, gq.x, gq.y);
        }
        s0[nt * 2] = __expf(ch[0] + cla[0] + clb[0]);
        s0[nt * 2 + 1] = __expf(ch[1] + cla[1] + clb[1]);
        s1[nt * 2] = __expf(ch[2] + cla[2] + clb[2]);
        s1[nt * 2 + 1] = __expf(ch[3] + cla[3] + clb[3]);
        ssum0 += s0[nt * 2] + s0[nt * 2 + 1];
        ssum1 += s1[nt * 2] + s1[nt * 2 + 1];
    }

    // ---- affine GEMM (1 MMA per nt, bias in accumulator init) ----
    float out0[10], out1[10];
    #pragma unroll
    for (int i = 0; i < 10; i++) { out0[i] = 0.0f; out1[i] = 0.0f; }
    #pragma unroll
    for (int nt = 0; nt < 40; nt++) {
        uint2 bq = sBF[nt * 32 + lane];
        float2 bs = sBias[nt * 4 + t];
        float c[4] = {bs.x, bs.y, bs.x, bs.y};
        mma_f16(c, xh, bq.x, bq.y);
        const int o = nt >> 2;          // compile-time under full unroll
        const int j2 = (nt & 3) * 2;
        out0[o] += s0[j2] * c[0] + s0[j2 + 1] * c[1];
        out1[o] += s1[j2] * c[2] + s1[j2 + 1] * c[3];
    }

    // ---- reduce across the 4 lanes of each group (t dimension) ----
    #pragma unroll
    for (int m = 1; m <= 2; m <<= 1) {
        #pragma unroll
        for (int i = 0; i < 10; i++) {
            out0[i] += __shfl_xor_sync(0xffffffffu, out0[i], m);
            out1[i] += __shfl_xor_sync(0xffffffffu, out1[i], m);
        }
        ssum0 += __shfl_xor_sync(0xffffffffu, ssum0, m);
        ssum1 += __shfl_xor_sync(0xffffffffu, ssum1, m);
    }

    // ---- finalize (t==0 lanes own rows ws+g and ws+g+8) ----
    if (t == 0) {
        const size_t base = (size_t)blockIdx.x * SPC;
        finish_sample(out0, ssum0, out + (base + ws + g) * OO);
        finish_sample(out1, ssum1, out + (base + ws + g + 8) * OO);
    }
}

extern "C" void kernel_launch(void* const* d_in, const int* in_sizes, int n_in,
                              void* d_out, int out_size) {
    const float* X = (const float*)d_in[0];
    const float* centers = (const float*)d_in[1];
    const float* sigmas = (const float*)d_in[2];
    const float* coeffs = (const float*)d_in[3];
    float* out = (float*)d_out;

    prep_kernel<<<7, 256>>>(centers, sigmas, coeffs);
    anfis_kernel<<<GRID, TPB>>>(X, out);
}